// round 10
// baseline (speedup 1.0000x reference)
#include <cuda_runtime.h>
#include <cstdint>

#define SEQ   4096
#define BATCH 64
#define DIM   96
#define HID   128
#define NROWS (SEQ*BATCH)

using u64 = unsigned long long;

// ---------------- scratch (static device globals) ---------------------------
__device__ float g_zx0[(size_t)NROWS*1024 + 65536];  // [row=t*64+b][n], +1 step pad
__device__ float g_zx1[(size_t)NROWS*1024 + 65536];
__device__ float g_ys0[(size_t)NROWS*256];           // [t][b][2H]
__device__ float g_ys1[(size_t)NROWS*256];

// ---------------- helpers ----------------------------------------------------
__device__ __forceinline__ float sigm(float x)   { return 1.f/(1.f+__expf(-x)); }
__device__ __forceinline__ float tanh_s(float x) { float e=__expf(2.f*x); return 1.f-2.f/(e+1.f); }
__device__ __forceinline__ void ffma2(u64 &d, u64 a, u64 b) {
    asm volatile("fma.rn.f32x2 %0, %1, %2, %0;" : "+l"(d) : "l"(a), "l"(b));
}
__device__ __forceinline__ void lds2(u64 &a, u64 &b, uint32_t addr) {
    asm volatile("ld.shared.v2.u64 {%0,%1}, [%2];" : "=l"(a), "=l"(b) : "r"(addr));
}
__device__ __forceinline__ void unpk(float &lo, float &hi, u64 v) {
    asm volatile("mov.b64 {%0,%1}, %2;" : "=f"(lo), "=f"(hi) : "l"(v));
}
__device__ __forceinline__ uint32_t f2tf32(float x) {
    uint32_t r; asm("cvt.rna.tf32.f32 %0, %1;" : "=r"(r) : "f"(x)); return r;
}
__device__ __forceinline__ void mma_tf32(float4 &c,
    uint32_t a0, uint32_t a1, uint32_t a2, uint32_t a3,
    uint32_t b0, uint32_t b1)
{
    asm volatile("mma.sync.aligned.m16n8k8.row.col.f32.tf32.tf32.f32 "
        "{%0,%1,%2,%3}, {%4,%5,%6,%7}, {%8,%9}, {%0,%1,%2,%3};"
        : "+f"(c.x), "+f"(c.y), "+f"(c.z), "+f"(c.w)
        : "r"(a0), "r"(a1), "r"(a2), "r"(a3), "r"(b0), "r"(b1));
}

// ---------------- input-projection GEMM: round-5 proven version --------------
template<int K, int LAYER>
__global__ void __launch_bounds__(256) mma_gemm(
    const float* __restrict__ Aext,
    const float* __restrict__ Wf, const float* __restrict__ Wb,
    const float* __restrict__ bf, const float* __restrict__ bb)
{
    __shared__ uint32_t As[128][36];
    __shared__ uint32_t Ws[128][36];

    const float* A = (LAYER == 0) ? Aext : (const float*)g_ys0;
    float*       Z = LAYER ? g_zx1 : g_zx0;

    const int n0 = blockIdx.x * 128;
    const int m0 = blockIdx.y * 128;
    const float* W    = (n0 < 512) ? (Wf + (size_t)n0*K) : (Wb + (size_t)(n0-512)*K);
    const float* bias = (n0 < 512) ? (bf + n0) : (bb + (n0-512));

    const int tid  = threadIdx.x;
    const int wid  = tid >> 5, lane = tid & 31;
    const int wm   = wid & 3,  wn   = wid >> 2;
    const int g    = lane >> 2, t   = lane & 3;

    float4 acc[2][8];
#pragma unroll
    for (int mi = 0; mi < 2; mi++)
#pragma unroll
        for (int ni = 0; ni < 8; ni++) acc[mi][ni] = make_float4(0.f,0.f,0.f,0.f);

    for (int k0 = 0; k0 < K; k0 += 32) {
#pragma unroll
        for (int i = 0; i < 4; i++) {
            int q = tid + i*256;
            int r = q >> 3, kq = q & 7;
            float4 av = *(const float4*)(A + (size_t)(m0+r)*K + k0 + kq*4);
            uint4 ua = { f2tf32(av.x), f2tf32(av.y), f2tf32(av.z), f2tf32(av.w) };
            *(uint4*)&As[r][kq*4] = ua;
            float4 wv = *(const float4*)(W + (size_t)r*K + k0 + kq*4);
            uint4 uw = { f2tf32(wv.x), f2tf32(wv.y), f2tf32(wv.z), f2tf32(wv.w) };
            *(uint4*)&Ws[r][kq*4] = uw;
        }
        __syncthreads();
#pragma unroll
        for (int kb = 0; kb < 32; kb += 8) {
            uint32_t a[2][4];
#pragma unroll
            for (int mi = 0; mi < 2; mi++) {
                int R = wm*32 + mi*16;
                a[mi][0] = As[R + g    ][kb + t    ];
                a[mi][1] = As[R + g + 8][kb + t    ];
                a[mi][2] = As[R + g    ][kb + t + 4];
                a[mi][3] = As[R + g + 8][kb + t + 4];
            }
#pragma unroll
            for (int ni = 0; ni < 8; ni++) {
                int N8 = wn*64 + ni*8;
                uint32_t b0 = Ws[N8 + g][kb + t    ];
                uint32_t b1 = Ws[N8 + g][kb + t + 4];
                mma_tf32(acc[0][ni], a[0][0], a[0][1], a[0][2], a[0][3], b0, b1);
                mma_tf32(acc[1][ni], a[1][0], a[1][1], a[1][2], a[1][3], b0, b1);
            }
        }
        __syncthreads();
    }

#pragma unroll
    for (int ni = 0; ni < 8; ni++) {
        int ncl = wn*64 + ni*8 + 2*t;
        float2 bv = *(const float2*)(bias + ncl);
#pragma unroll
        for (int mi = 0; mi < 2; mi++) {
            float4 cf = acc[mi][ni];
            int r0 = m0 + wm*32 + mi*16 + g;
            float2 o0 = { cf.x + bv.x, cf.y + bv.y };
            float2 o1 = { cf.z + bv.x, cf.w + bv.y };
            *(float2*)(Z + (size_t)r0*1024 + n0 + ncl)     = o0;
            *(float2*)(Z + (size_t)(r0+8)*1024 + n0 + ncl) = o1;
        }
    }
}

// ---------------- recurrence: one CTA per (cell, batch) ----------------------
// 128 CTAs x 512 threads (R4 skeleton). Thread j owns Whh row j.
// k[0,96): 48 u64 weight pairs in registers (96 regs).
// k[96,128): 16 u64 weight pairs streamed per step via __ldg (L1-resident,
// LSU pipe) — removes the weight-LDS crossbar traffic entirely.
// h[128] smem broadcast; 4 accumulator chains.
template<int LAYER>
__global__ void __launch_bounds__(512, 1) recur_kernel(
    const float* __restrict__ whhf, const float* __restrict__ whhb)
{
    __shared__ float hs[128];
    __shared__ float zs[512];

    const int tid  = threadIdx.x;                   // = j (Whh row)
    const int cell = blockIdx.x >> 6;
    const int b    = blockIdx.x & 63;
    const float* whh = cell ? whhb : whhf;
    const float* zx  = LAYER ? g_zx1 : g_zx0;
    float*       ys  = LAYER ? g_ys1 : g_ys0;

    const u64* wrow  = (const u64*)whh + (size_t)tid*64;
    const u64* wtail = wrow + 48;                   // 16 u64, L1-hot after t=0
    u64 wreg[48];
#pragma unroll
    for (int q = 0; q < 48; q++) wreg[q] = __ldg(wrow + q);

    if (tid < 128) hs[tid] = 0.f;

    uint32_t hs_s = (uint32_t)__cvta_generic_to_shared(hs);

    const float* zptr = zx + (size_t)b*1024 + cell*512 + tid;
    float* ysp = ys + (size_t)b*256 + cell*128 + tid;
    float zcur = __ldcs(zptr);
    float c = 0.f;

    __syncthreads();

    for (int t = 0; t < SEQ; t++) {
        float znext = __ldcs(zptr + (size_t)(t+1)*65536);

        u64 a0 = 0ull, a1 = 0ull, a2 = 0ull, a3 = 0ull;
        // k in [96,128): weights via LDG (LSU), h via broadcast LDS
#pragma unroll
        for (int p = 0; p < 8; p++) {
            u64 wa = __ldg(wtail + 2*p);
            u64 wb = __ldg(wtail + 2*p + 1);
            u64 ha, hb;
            lds2(ha, hb, hs_s + 384 + p*16);
            ffma2(a0, wa, ha);
            ffma2(a1, wb, hb);
        }
        // k in [0,96): weights in registers
#pragma unroll
        for (int q = 0; q < 48; q += 2) {
            u64 ha, hb;
            lds2(ha, hb, hs_s + q*8);
            ffma2(a2, wreg[q],   ha);
            ffma2(a3, wreg[q+1], hb);
        }
        float x0,x1,x2,x3,y0,y1,y2,y3;
        unpk(x0,x1,a0); unpk(x2,x3,a1);
        unpk(y0,y1,a2); unpk(y2,y3,a3);
        zs[tid] = (((x0+x1)+(x2+x3)) + ((y0+y1)+(y2+y3))) + zcur;
        zcur = znext;
        __syncthreads();

        if (tid < 128) {
            float zi = zs[tid], zf = zs[128+tid], zg = zs[256+tid], zo = zs[384+tid];
            float ig = sigm(zi), fg = sigm(zf), gg = tanh_s(zg), og = sigm(zo);
            c = fg*c + ig*gg;
            float h = og * tanh_s(c);
            hs[tid] = h;
            ysp[(size_t)t*16384] = h;
        }
        __syncthreads();
    }
}

// ---------------- final FC + sigmoid ----------------------------------------
__global__ void __launch_bounds__(256) fc_kernel(
    const float* __restrict__ fcw, const float* __restrict__ fcb,
    float* __restrict__ out)
{
    int gtid = blockIdx.x*blockDim.x + threadIdx.x;
    int row = gtid >> 5, lane = gtid & 31;
    if (row >= NROWS) return;
    const float* y = g_ys1 + (size_t)row*256;
    float s = 0.f;
#pragma unroll
    for (int i = 0; i < 8; i++) s += y[lane + i*32] * __ldg(fcw + lane + i*32);
#pragma unroll
    for (int o = 16; o; o >>= 1) s += __shfl_xor_sync(0xffffffffu, s, o);
    if (lane == 0) out[row] = 1.f/(1.f + __expf(-(s + fcb[0])));
}

// ---------------- launch -----------------------------------------------------
extern "C" void kernel_launch(void* const* d_in, const int* in_sizes, int n_in,
                              void* d_out, int out_size)
{
    const float* x     = (const float*)d_in[0];
    const float* wih0f = (const float*)d_in[1];
    const float* whh0f = (const float*)d_in[2];
    const float* b0f   = (const float*)d_in[3];
    const float* wih0b = (const float*)d_in[4];
    const float* whh0b = (const float*)d_in[5];
    const float* b0b   = (const float*)d_in[6];
    const float* wih1f = (const float*)d_in[7];
    const float* whh1f = (const float*)d_in[8];
    const float* b1f   = (const float*)d_in[9];
    const float* wih1b = (const float*)d_in[10];
    const float* whh1b = (const float*)d_in[11];
    const float* b1b   = (const float*)d_in[12];
    const float* fcw   = (const float*)d_in[13];
    const float* fcb   = (const float*)d_in[14];
    float* out = (float*)d_out;

    dim3 ggrid(8, NROWS/128);
    mma_gemm<DIM, 0><<<ggrid, 256>>>(x, wih0f, wih0b, b0f, b0b);
    recur_kernel<0><<<128, 512>>>(whh0f, whh0b);

    mma_gemm<256, 1><<<ggrid, 256>>>(nullptr, wih1f, wih1b, b1f, b1b);
    recur_kernel<1><<<128, 512>>>(whh1f, whh1b);

    fc_kernel<<<(NROWS*32)/256, 256>>>(fcw, fcb, out);
}

// round 11
// speedup vs baseline: 3.6998x; 3.6998x over previous
#include <cuda_runtime.h>
#include <cstdint>

#define SEQ   4096
#define BATCH 64
#define DIM   96
#define HID   128
#define NROWS (SEQ*BATCH)

using u64 = unsigned long long;

// ---------------- scratch (static device globals) ---------------------------
__device__ float g_zx0[(size_t)NROWS*1024 + 65536];  // [row=t*64+b][n], +1 step pad
__device__ float g_zx1[(size_t)NROWS*1024 + 65536];
__device__ float g_ys0[(size_t)NROWS*256];           // [t][b][2H]
__device__ float g_ys1[(size_t)NROWS*256];

// ---------------- helpers ----------------------------------------------------
__device__ __forceinline__ float sigm(float x)   { return 1.f/(1.f+__expf(-x)); }
__device__ __forceinline__ float tanh_s(float x) { float e=__expf(2.f*x); return 1.f-2.f/(e+1.f); }
__device__ __forceinline__ void ffma2(u64 &d, u64 a, u64 b) {
    asm volatile("fma.rn.f32x2 %0, %1, %2, %0;" : "+l"(d) : "l"(a), "l"(b));
}
__device__ __forceinline__ void lds2(u64 &a, u64 &b, uint32_t addr) {
    asm volatile("ld.shared.v2.u64 {%0,%1}, [%2];" : "=l"(a), "=l"(b) : "r"(addr));
}
__device__ __forceinline__ u64 lds1(uint32_t addr) {
    u64 a; asm volatile("ld.shared.u64 %0, [%1];" : "=l"(a) : "r"(addr)); return a;
}
__device__ __forceinline__ void unpk(float &lo, float &hi, u64 v) {
    asm volatile("mov.b64 {%0,%1}, %2;" : "=f"(lo), "=f"(hi) : "l"(v));
}
__device__ __forceinline__ uint32_t f2tf32(float x) {
    uint32_t r; asm("cvt.rna.tf32.f32 %0, %1;" : "=r"(r) : "f"(x)); return r;
}
__device__ __forceinline__ void mma_tf32(float4 &c,
    uint32_t a0, uint32_t a1, uint32_t a2, uint32_t a3,
    uint32_t b0, uint32_t b1)
{
    asm volatile("mma.sync.aligned.m16n8k8.row.col.f32.tf32.tf32.f32 "
        "{%0,%1,%2,%3}, {%4,%5,%6,%7}, {%8,%9}, {%0,%1,%2,%3};"
        : "+f"(c.x), "+f"(c.y), "+f"(c.z), "+f"(c.w)
        : "r"(a0), "r"(a1), "r"(a2), "r"(a3), "r"(b0), "r"(b1));
}

// ---------------- input-projection GEMM: round-5 proven version --------------
template<int K, int LAYER>
__global__ void __launch_bounds__(256) mma_gemm(
    const float* __restrict__ Aext,
    const float* __restrict__ Wf, const float* __restrict__ Wb,
    const float* __restrict__ bf, const float* __restrict__ bb)
{
    __shared__ uint32_t As[128][36];
    __shared__ uint32_t Ws[128][36];

    const float* A = (LAYER == 0) ? Aext : (const float*)g_ys0;
    float*       Z = LAYER ? g_zx1 : g_zx0;

    const int n0 = blockIdx.x * 128;
    const int m0 = blockIdx.y * 128;
    const float* W    = (n0 < 512) ? (Wf + (size_t)n0*K) : (Wb + (size_t)(n0-512)*K);
    const float* bias = (n0 < 512) ? (bf + n0) : (bb + (n0-512));

    const int tid  = threadIdx.x;
    const int wid  = tid >> 5, lane = tid & 31;
    const int wm   = wid & 3,  wn   = wid >> 2;
    const int g    = lane >> 2, t   = lane & 3;

    float4 acc[2][8];
#pragma unroll
    for (int mi = 0; mi < 2; mi++)
#pragma unroll
        for (int ni = 0; ni < 8; ni++) acc[mi][ni] = make_float4(0.f,0.f,0.f,0.f);

    for (int k0 = 0; k0 < K; k0 += 32) {
#pragma unroll
        for (int i = 0; i < 4; i++) {
            int q = tid + i*256;
            int r = q >> 3, kq = q & 7;
            float4 av = *(const float4*)(A + (size_t)(m0+r)*K + k0 + kq*4);
            uint4 ua = { f2tf32(av.x), f2tf32(av.y), f2tf32(av.z), f2tf32(av.w) };
            *(uint4*)&As[r][kq*4] = ua;
            float4 wv = *(const float4*)(W + (size_t)r*K + k0 + kq*4);
            uint4 uw = { f2tf32(wv.x), f2tf32(wv.y), f2tf32(wv.z), f2tf32(wv.w) };
            *(uint4*)&Ws[r][kq*4] = uw;
        }
        __syncthreads();
#pragma unroll
        for (int kb = 0; kb < 32; kb += 8) {
            uint32_t a[2][4];
#pragma unroll
            for (int mi = 0; mi < 2; mi++) {
                int R = wm*32 + mi*16;
                a[mi][0] = As[R + g    ][kb + t    ];
                a[mi][1] = As[R + g + 8][kb + t    ];
                a[mi][2] = As[R + g    ][kb + t + 4];
                a[mi][3] = As[R + g + 8][kb + t + 4];
            }
#pragma unroll
            for (int ni = 0; ni < 8; ni++) {
                int N8 = wn*64 + ni*8;
                uint32_t b0 = Ws[N8 + g][kb + t    ];
                uint32_t b1 = Ws[N8 + g][kb + t + 4];
                mma_tf32(acc[0][ni], a[0][0], a[0][1], a[0][2], a[0][3], b0, b1);
                mma_tf32(acc[1][ni], a[1][0], a[1][1], a[1][2], a[1][3], b0, b1);
            }
        }
        __syncthreads();
    }

#pragma unroll
    for (int ni = 0; ni < 8; ni++) {
        int ncl = wn*64 + ni*8 + 2*t;
        float2 bv = *(const float2*)(bias + ncl);
#pragma unroll
        for (int mi = 0; mi < 2; mi++) {
            float4 cf = acc[mi][ni];
            int r0 = m0 + wm*32 + mi*16 + g;
            float2 o0 = { cf.x + bv.x, cf.y + bv.y };
            float2 o1 = { cf.z + bv.x, cf.w + bv.y };
            *(float2*)(Z + (size_t)r0*1024 + n0 + ncl)     = o0;
            *(float2*)(Z + (size_t)(r0+8)*1024 + n0 + ncl) = o1;
        }
    }
}

// ---------------- recurrence: one CTA per (cell, batch) ----------------------
// 128 CTAs x 512 threads. Warp w owns units [8w, 8w+8); lane l = gate*8+uoff,
// i.e. thread row = (l>>3)*128 + w*8 + (l&7). k-loop identical to R4:
// k[0,96) weights in 48 reg pairs, k[96,128) in smem [16 kp][512 tid].
// Epilogue: 4 shfl.idx gather the unit's gates in-warp; every lane computes
// (c,h) redundantly; lanes 0..7 write h + ys. Double-buffered h -> ONE
// __syncthreads per step.
#define RSMEM (65536 + 1024)

template<int LAYER>
__global__ void __launch_bounds__(512, 1) recur_kernel(
    const float* __restrict__ whhf, const float* __restrict__ whhb)
{
    extern __shared__ char smraw[];
    u64*   wsm = (u64*)smraw;                       // [16 kp][512 tid]
    float* hs  = (float*)(smraw + 65536);           // [2][128] double buffer

    const int tid  = threadIdx.x;
    const int w    = tid >> 5;
    const int l    = tid & 31;
    const int uoff = l & 7;
    const int row  = (l >> 3)*128 + w*8 + uoff;     // Whh row (gate*128 + unit)
    const int u    = w*8 + uoff;                    // unit
    const int cell = blockIdx.x >> 6;
    const int b    = blockIdx.x & 63;
    const float* whh = cell ? whhb : whhf;
    const float* zx  = LAYER ? g_zx1 : g_zx0;
    float*       ys  = LAYER ? g_ys1 : g_ys0;

    const u64* wrow = (const u64*)whh + (size_t)row*64;
    u64 wreg[48];
#pragma unroll
    for (int q = 0; q < 48; q++) wreg[q] = __ldg(wrow + q);
#pragma unroll
    for (int q = 0; q < 16; q++) wsm[q*512 + tid] = __ldg(wrow + 48 + q);

    if (tid < 128) hs[tid] = 0.f;                   // read buffer for t=0

    uint32_t hs_s  = (uint32_t)__cvta_generic_to_shared(hs);
    uint32_t wsm_s = (uint32_t)__cvta_generic_to_shared(wsm);

    const float* zptr = zx + (size_t)b*1024 + cell*512 + row;
    float* ysp = ys + (size_t)b*256 + cell*128 + u;
    float zcur = __ldcs(zptr);
    float c = 0.f;

    __syncthreads();

    for (int t = 0; t < SEQ; t++) {
        float znext = __ldcs(zptr + (size_t)(t+1)*65536);
        uint32_t hb = hs_s + (t & 1)*512;           // current read buffer

        u64 a0 = 0ull, a1 = 0ull, a2 = 0ull, a3 = 0ull;
#pragma unroll
        for (int q = 0; q < 48; q += 2) {                   // k in [0,96)
            u64 ha, hbv;
            lds2(ha, hbv, hb + q*8);
            ffma2(a0, wreg[q],   ha);
            ffma2(a1, wreg[q+1], hbv);
        }
#pragma unroll
        for (int kp = 0; kp < 16; kp += 2) {                // k in [96,128)
            u64 ha, hbv;
            lds2(ha, hbv, hb + 384 + kp*8);
            u64 wa = lds1(wsm_s + (kp*512     + tid)*8);
            u64 wb = lds1(wsm_s + ((kp+1)*512 + tid)*8);
            ffma2(a2, wa, ha);
            ffma2(a3, wb, hbv);
        }
        float x0,x1,x2,x3,y0,y1,y2,y3;
        unpk(x0,x1,a0); unpk(x2,x3,a1);
        unpk(y0,y1,a2); unpk(y2,y3,a3);
        float s = (((x0+x1)+(x2+x3)) + ((y0+y1)+(y2+y3))) + zcur;
        zcur = znext;

        // gather this unit's 4 gate pre-activations (all in this warp)
        float zi = __shfl_sync(0xffffffffu, s, uoff);
        float zf = __shfl_sync(0xffffffffu, s, uoff | 8);
        float zg = __shfl_sync(0xffffffffu, s, uoff | 16);
        float zo = __shfl_sync(0xffffffffu, s, uoff | 24);
        float ig = sigm(zi), fg = sigm(zf), gg = tanh_s(zg), og = sigm(zo);
        c = fg*c + ig*gg;                           // redundant across 4 lanes
        float h = og * tanh_s(c);
        if (l < 8) {
            ((float*)(smraw + 65536))[((t+1)&1)*128 + u] = h;
            ysp[(size_t)t*16384] = h;
        }
        __syncthreads();
    }
}

// ---------------- final FC + sigmoid ----------------------------------------
__global__ void __launch_bounds__(256) fc_kernel(
    const float* __restrict__ fcw, const float* __restrict__ fcb,
    float* __restrict__ out)
{
    int gtid = blockIdx.x*blockDim.x + threadIdx.x;
    int row = gtid >> 5, lane = gtid & 31;
    if (row >= NROWS) return;
    const float* y = g_ys1 + (size_t)row*256;
    float s = 0.f;
#pragma unroll
    for (int i = 0; i < 8; i++) s += y[lane + i*32] * __ldg(fcw + lane + i*32);
#pragma unroll
    for (int o = 16; o; o >>= 1) s += __shfl_xor_sync(0xffffffffu, s, o);
    if (lane == 0) out[row] = 1.f/(1.f + __expf(-(s + fcb[0])));
}

// ---------------- launch -----------------------------------------------------
extern "C" void kernel_launch(void* const* d_in, const int* in_sizes, int n_in,
                              void* d_out, int out_size)
{
    const float* x     = (const float*)d_in[0];
    const float* wih0f = (const float*)d_in[1];
    const float* whh0f = (const float*)d_in[2];
    const float* b0f   = (const float*)d_in[3];
    const float* wih0b = (const float*)d_in[4];
    const float* whh0b = (const float*)d_in[5];
    const float* b0b   = (const float*)d_in[6];
    const float* wih1f = (const float*)d_in[7];
    const float* whh1f = (const float*)d_in[8];
    const float* b1f   = (const float*)d_in[9];
    const float* wih1b = (const float*)d_in[10];
    const float* whh1b = (const float*)d_in[11];
    const float* b1b   = (const float*)d_in[12];
    const float* fcw   = (const float*)d_in[13];
    const float* fcb   = (const float*)d_in[14];
    float* out = (float*)d_out;

    cudaFuncSetAttribute(recur_kernel<0>, cudaFuncAttributeMaxDynamicSharedMemorySize, RSMEM);
    cudaFuncSetAttribute(recur_kernel<1>, cudaFuncAttributeMaxDynamicSharedMemorySize, RSMEM);

    dim3 ggrid(8, NROWS/128);
    mma_gemm<DIM, 0><<<ggrid, 256>>>(x, wih0f, wih0b, b0f, b0b);
    recur_kernel<0><<<128, 512, RSMEM>>>(whh0f, whh0b);

    mma_gemm<256, 1><<<ggrid, 256>>>(nullptr, wih1f, wih1b, b1f, b1b);
    recur_kernel<1><<<128, 512, RSMEM>>>(whh1f, whh1b);

    fc_kernel<<<(NROWS*32)/256, 256>>>(fcw, fcb, out);
}

// round 12
// speedup vs baseline: 4.5131x; 1.2198x over previous
#include <cuda_runtime.h>
#include <cstdint>

#define SEQ   4096
#define BATCH 64
#define DIM   96
#define HID   128
#define NROWS (SEQ*BATCH)

using u64 = unsigned long long;

// ---------------- scratch (static device globals) ---------------------------
__device__ float g_zx0[(size_t)NROWS*1024 + 65536];  // [row=t*64+b][n], +1 step pad
__device__ float g_zx1[(size_t)NROWS*1024 + 65536];
__device__ float g_ys0[(size_t)NROWS*256];           // [t][b][2H]
__device__ float g_ys1[(size_t)NROWS*256];

// ---------------- helpers ----------------------------------------------------
__device__ __forceinline__ float sigm(float x)   { return 1.f/(1.f+__expf(-x)); }
__device__ __forceinline__ float tanha(float x)  {
    float r; asm("tanh.approx.f32 %0, %1;" : "=f"(r) : "f"(x)); return r;
}
__device__ __forceinline__ float sigma_fast(float x) {
    return fmaf(0.5f, tanha(0.5f*x), 0.5f);
}
__device__ __forceinline__ void ffma2(u64 &d, u64 a, u64 b) {
    asm volatile("fma.rn.f32x2 %0, %1, %2, %0;" : "+l"(d) : "l"(a), "l"(b));
}
__device__ __forceinline__ void lds2(u64 &a, u64 &b, uint32_t addr) {
    asm volatile("ld.shared.v2.u64 {%0,%1}, [%2];" : "=l"(a), "=l"(b) : "r"(addr));
}
__device__ __forceinline__ void unpk(float &lo, float &hi, u64 v) {
    asm volatile("mov.b64 {%0,%1}, %2;" : "=f"(lo), "=f"(hi) : "l"(v));
}
__device__ __forceinline__ uint32_t f2tf32(float x) {
    uint32_t r; asm("cvt.rna.tf32.f32 %0, %1;" : "=r"(r) : "f"(x)); return r;
}
__device__ __forceinline__ void mma_tf32(float4 &c,
    uint32_t a0, uint32_t a1, uint32_t a2, uint32_t a3,
    uint32_t b0, uint32_t b1)
{
    asm volatile("mma.sync.aligned.m16n8k8.row.col.f32.tf32.tf32.f32 "
        "{%0,%1,%2,%3}, {%4,%5,%6,%7}, {%8,%9}, {%0,%1,%2,%3};"
        : "+f"(c.x), "+f"(c.y), "+f"(c.z), "+f"(c.w)
        : "r"(a0), "r"(a1), "r"(a2), "r"(a3), "r"(b0), "r"(b1));
}

// ---------------- input-projection GEMM: round-5 proven version --------------
template<int K, int LAYER>
__global__ void __launch_bounds__(256) mma_gemm(
    const float* __restrict__ Aext,
    const float* __restrict__ Wf, const float* __restrict__ Wb,
    const float* __restrict__ bf, const float* __restrict__ bb)
{
    __shared__ uint32_t As[128][36];
    __shared__ uint32_t Ws[128][36];

    const float* A = (LAYER == 0) ? Aext : (const float*)g_ys0;
    float*       Z = LAYER ? g_zx1 : g_zx0;

    const int n0 = blockIdx.x * 128;
    const int m0 = blockIdx.y * 128;
    const float* W    = (n0 < 512) ? (Wf + (size_t)n0*K) : (Wb + (size_t)(n0-512)*K);
    const float* bias = (n0 < 512) ? (bf + n0) : (bb + (n0-512));

    const int tid  = threadIdx.x;
    const int wid  = tid >> 5, lane = tid & 31;
    const int wm   = wid & 3,  wn   = wid >> 2;
    const int g    = lane >> 2, t   = lane & 3;

    float4 acc[2][8];
#pragma unroll
    for (int mi = 0; mi < 2; mi++)
#pragma unroll
        for (int ni = 0; ni < 8; ni++) acc[mi][ni] = make_float4(0.f,0.f,0.f,0.f);

    for (int k0 = 0; k0 < K; k0 += 32) {
#pragma unroll
        for (int i = 0; i < 4; i++) {
            int q = tid + i*256;
            int r = q >> 3, kq = q & 7;
            float4 av = *(const float4*)(A + (size_t)(m0+r)*K + k0 + kq*4);
            uint4 ua = { f2tf32(av.x), f2tf32(av.y), f2tf32(av.z), f2tf32(av.w) };
            *(uint4*)&As[r][kq*4] = ua;
            float4 wv = *(const float4*)(W + (size_t)r*K + k0 + kq*4);
            uint4 uw = { f2tf32(wv.x), f2tf32(wv.y), f2tf32(wv.z), f2tf32(wv.w) };
            *(uint4*)&Ws[r][kq*4] = uw;
        }
        __syncthreads();
#pragma unroll
        for (int kb = 0; kb < 32; kb += 8) {
            uint32_t a[2][4];
#pragma unroll
            for (int mi = 0; mi < 2; mi++) {
                int R = wm*32 + mi*16;
                a[mi][0] = As[R + g    ][kb + t    ];
                a[mi][1] = As[R + g + 8][kb + t    ];
                a[mi][2] = As[R + g    ][kb + t + 4];
                a[mi][3] = As[R + g + 8][kb + t + 4];
            }
#pragma unroll
            for (int ni = 0; ni < 8; ni++) {
                int N8 = wn*64 + ni*8;
                uint32_t b0 = Ws[N8 + g][kb + t    ];
                uint32_t b1 = Ws[N8 + g][kb + t + 4];
                mma_tf32(acc[0][ni], a[0][0], a[0][1], a[0][2], a[0][3], b0, b1);
                mma_tf32(acc[1][ni], a[1][0], a[1][1], a[1][2], a[1][3], b0, b1);
            }
        }
        __syncthreads();
    }

#pragma unroll
    for (int ni = 0; ni < 8; ni++) {
        int ncl = wn*64 + ni*8 + 2*t;
        float2 bv = *(const float2*)(bias + ncl);
#pragma unroll
        for (int mi = 0; mi < 2; mi++) {
            float4 cf = acc[mi][ni];
            int r0 = m0 + wm*32 + mi*16 + g;
            float2 o0 = { cf.x + bv.x, cf.y + bv.y };
            float2 o1 = { cf.z + bv.x, cf.w + bv.y };
            *(float2*)(Z + (size_t)r0*1024 + n0 + ncl)     = o0;
            *(float2*)(Z + (size_t)(r0+8)*1024 + n0 + ncl) = o1;
        }
    }
}

// ---------------- recurrence: one CTA per (cell, batch) ----------------------
// 128 CTAs x 512 threads. Warp w owns units [8w, 8w+8); lane l = gate*8+uoff,
// thread row = (l>>3)*128 + w*8 + (l&7). k[0,96): 48 reg weight pairs.
// k[96,128): smem weights interleaved [8 p][512 tid][2 u64] -> 8 LDS.128/step.
// Epilogue: 4 shfl.idx gather gates in-warp; tanh.approx nonlinearity (5 MUFU
// per thread vs 10); lanes 0..7 write h + ys. Double-buffered h, 1 bar/step.
#define RSMEM (65536 + 1024)

template<int LAYER>
__global__ void __launch_bounds__(512, 1) recur_kernel(
    const float* __restrict__ whhf, const float* __restrict__ whhb)
{
    extern __shared__ char smraw[];
    u64*   wsm = (u64*)smraw;                       // [8 p][512 tid][2]
    float* hs  = (float*)(smraw + 65536);           // [2][128] double buffer

    const int tid  = threadIdx.x;
    const int w    = tid >> 5;
    const int l    = tid & 31;
    const int uoff = l & 7;
    const int row  = (l >> 3)*128 + w*8 + uoff;     // Whh row (gate*128 + unit)
    const int u    = w*8 + uoff;                    // unit
    const int cell = blockIdx.x >> 6;
    const int b    = blockIdx.x & 63;
    const float* whh = cell ? whhb : whhf;
    const float* zx  = LAYER ? g_zx1 : g_zx0;
    float*       ys  = LAYER ? g_ys1 : g_ys0;

    const u64* wrow = (const u64*)whh + (size_t)row*64;
    u64 wreg[48];
#pragma unroll
    for (int q = 0; q < 48; q++) wreg[q] = __ldg(wrow + q);
#pragma unroll
    for (int p = 0; p < 8; p++) {
        wsm[(p*512 + tid)*2 + 0] = __ldg(wrow + 48 + 2*p);
        wsm[(p*512 + tid)*2 + 1] = __ldg(wrow + 48 + 2*p + 1);
    }

    if (tid < 128) hs[tid] = 0.f;                   // read buffer for t=0

    uint32_t hs_s  = (uint32_t)__cvta_generic_to_shared(hs);
    uint32_t wsm_s = (uint32_t)__cvta_generic_to_shared(wsm);

    const float* zptr = zx + (size_t)b*1024 + cell*512 + row;
    float* ysp = ys + (size_t)b*256 + cell*128 + u;
    float zcur = __ldcs(zptr);
    float c = 0.f;

    __syncthreads();

    for (int t = 0; t < SEQ; t++) {
        float znext = __ldcs(zptr + (size_t)(t+1)*65536);
        uint32_t hb = hs_s + (t & 1)*512;           // current read buffer

        u64 a0 = 0ull, a1 = 0ull, a2 = 0ull, a3 = 0ull;
#pragma unroll
        for (int q = 0; q < 48; q += 2) {                   // k in [0,96)
            u64 ha, hbv;
            lds2(ha, hbv, hb + q*8);
            ffma2(a0, wreg[q],   ha);
            ffma2(a1, wreg[q+1], hbv);
        }
#pragma unroll
        for (int p = 0; p < 8; p++) {                       // k in [96,128)
            u64 ha, hbv, wa, wb;
            lds2(ha, hbv, hb + 384 + p*16);
            lds2(wa, wb, wsm_s + (p*512 + tid)*16);
            ffma2(a2, wa, ha);
            ffma2(a3, wb, hbv);
        }
        float x0,x1,x2,x3,y0,y1,y2,y3;
        unpk(x0,x1,a0); unpk(x2,x3,a1);
        unpk(y0,y1,a2); unpk(y2,y3,a3);
        float s = (((x0+x1)+(x2+x3)) + ((y0+y1)+(y2+y3))) + zcur;
        zcur = znext;

        // gather this unit's 4 gate pre-activations (all in this warp)
        float zi = __shfl_sync(0xffffffffu, s, uoff);
        float zf = __shfl_sync(0xffffffffu, s, uoff | 8);
        float zg = __shfl_sync(0xffffffffu, s, uoff | 16);
        float zo = __shfl_sync(0xffffffffu, s, uoff | 24);
        float ig = sigma_fast(zi), fg = sigma_fast(zf);
        float gg = tanha(zg),      og = sigma_fast(zo);
        c = fg*c + ig*gg;                           // redundant across 4 lanes
        float h = og * tanha(c);
        if (l < 8) {
            ((float*)(smraw + 65536))[((t+1)&1)*128 + u] = h;
            ysp[(size_t)t*16384] = h;
        }
        __syncthreads();
    }
}

// ---------------- final FC + sigmoid ----------------------------------------
__global__ void __launch_bounds__(256) fc_kernel(
    const float* __restrict__ fcw, const float* __restrict__ fcb,
    float* __restrict__ out)
{
    int gtid = blockIdx.x*blockDim.x + threadIdx.x;
    int row = gtid >> 5, lane = gtid & 31;
    if (row >= NROWS) return;
    const float* y = g_ys1 + (size_t)row*256;
    float s = 0.f;
#pragma unroll
    for (int i = 0; i < 8; i++) s += y[lane + i*32] * __ldg(fcw + lane + i*32);
#pragma unroll
    for (int o = 16; o; o >>= 1) s += __shfl_xor_sync(0xffffffffu, s, o);
    if (lane == 0) out[row] = sigm(s + fcb[0]);
}

// ---------------- launch -----------------------------------------------------
extern "C" void kernel_launch(void* const* d_in, const int* in_sizes, int n_in,
                              void* d_out, int out_size)
{
    const float* x     = (const float*)d_in[0];
    const float* wih0f = (const float*)d_in[1];
    const float* whh0f = (const float*)d_in[2];
    const float* b0f   = (const float*)d_in[3];
    const float* wih0b = (const float*)d_in[4];
    const float* whh0b = (const float*)d_in[5];
    const float* b0b   = (const float*)d_in[6];
    const float* wih1f = (const float*)d_in[7];
    const float* whh1f = (const float*)d_in[8];
    const float* b1f   = (const float*)d_in[9];
    const float* wih1b = (const float*)d_in[10];
    const float* whh1b = (const float*)d_in[11];
    const float* b1b   = (const float*)d_in[12];
    const float* fcw   = (const float*)d_in[13];
    const float* fcb   = (const float*)d_in[14];
    float* out = (float*)d_out;

    cudaFuncSetAttribute(recur_kernel<0>, cudaFuncAttributeMaxDynamicSharedMemorySize, RSMEM);
    cudaFuncSetAttribute(recur_kernel<1>, cudaFuncAttributeMaxDynamicSharedMemorySize, RSMEM);

    dim3 ggrid(8, NROWS/128);
    mma_gemm<DIM, 0><<<ggrid, 256>>>(x, wih0f, wih0b, b0f, b0b);
    recur_kernel<0><<<128, 512, RSMEM>>>(whh0f, whh0b);

    mma_gemm<256, 1><<<ggrid, 256>>>(nullptr, wih1f, wih1b, b1f, b1b);
    recur_kernel<1><<<128, 512, RSMEM>>>(whh1f, whh1b);

    fc_kernel<<<(NROWS*32)/256, 256>>>(fcw, fcb, out);
}

// round 13
// speedup vs baseline: 4.5780x; 1.0144x over previous
#include <cuda_runtime.h>
#include <cstdint>

#define SEQ   4096
#define BATCH 64
#define DIM   96
#define HID   128
#define NROWS (SEQ*BATCH)

using u64 = unsigned long long;

// ---------------- scratch (static device globals) ---------------------------
__device__ float g_zx0[(size_t)NROWS*1024 + 65536];  // [row=t*64+b][n], +1 step pad
__device__ float g_zx1[(size_t)NROWS*1024 + 65536];
__device__ float g_ys0[(size_t)NROWS*256];           // [t][b][2H]
__device__ float g_ys1[(size_t)NROWS*256];

// ---------------- helpers ----------------------------------------------------
__device__ __forceinline__ float sigm(float x)   { return 1.f/(1.f+__expf(-x)); }
__device__ __forceinline__ float tanha(float x)  {
    float r; asm("tanh.approx.f32 %0, %1;" : "=f"(r) : "f"(x)); return r;
}
__device__ __forceinline__ float sigma_fast(float x) {
    return fmaf(0.5f, tanha(0.5f*x), 0.5f);
}
__device__ __forceinline__ void ffma2(u64 &d, u64 a, u64 b) {
    asm volatile("fma.rn.f32x2 %0, %1, %2, %0;" : "+l"(d) : "l"(a), "l"(b));
}
__device__ __forceinline__ void lds2(u64 &a, u64 &b, uint32_t addr) {
    asm volatile("ld.shared.v2.u64 {%0,%1}, [%2];" : "=l"(a), "=l"(b) : "r"(addr));
}
__device__ __forceinline__ void unpk(float &lo, float &hi, u64 v) {
    asm volatile("mov.b64 {%0,%1}, %2;" : "=f"(lo), "=f"(hi) : "l"(v));
}
__device__ __forceinline__ void cpasync16(uint32_t dst, const void* src) {
    asm volatile("cp.async.ca.shared.global [%0], [%1], 16;" :: "r"(dst), "l"(src));
}
__device__ __forceinline__ void mma_tf32(float4 &c,
    uint32_t a0, uint32_t a1, uint32_t a2, uint32_t a3,
    uint32_t b0, uint32_t b1)
{
    asm volatile("mma.sync.aligned.m16n8k8.row.col.f32.tf32.tf32.f32 "
        "{%0,%1,%2,%3}, {%4,%5,%6,%7}, {%8,%9}, {%0,%1,%2,%3};"
        : "+f"(c.x), "+f"(c.y), "+f"(c.z), "+f"(c.w)
        : "r"(a0), "r"(a1), "r"(a2), "r"(a3), "r"(b0), "r"(b1));
}

// ---------------- input-projection GEMM: cp.async 2-stage pipeline -----------
// Z[row][n] = bias[n] + sum_k A[row][k]*W[n][k].  CTA 128Mx128N, K-tile 32,
// 8 warps = 4Mx2N. f32 fed directly to mma.tf32 (HW truncates) — no cvt/STS.
// Dynamic smem: As[2][128][36] + Ws[2][128][36] = 73728 B; 2 CTAs/SM.
#define GSTG 4608                 // words per stage (128*36)
#define GSMEM (4*GSTG*4)

template<int K, int LAYER>
__global__ void __launch_bounds__(256, 2) mma_gemm(
    const float* __restrict__ Aext,
    const float* __restrict__ Wf, const float* __restrict__ Wb,
    const float* __restrict__ bf, const float* __restrict__ bb)
{
    extern __shared__ uint32_t gsm[];          // As then Ws
    uint32_t* As = gsm;                        // [2][128][36]
    uint32_t* Ws = gsm + 2*GSTG;               // [2][128][36]

    const float* A = (LAYER == 0) ? Aext : (const float*)g_ys0;
    float*       Z = LAYER ? g_zx1 : g_zx0;

    const int n0 = blockIdx.x * 128;
    const int m0 = blockIdx.y * 128;
    const float* W    = (n0 < 512) ? (Wf + (size_t)n0*K) : (Wb + (size_t)(n0-512)*K);
    const float* bias = (n0 < 512) ? (bf + n0) : (bb + (n0-512));

    const int tid  = threadIdx.x;
    const int wid  = tid >> 5, lane = tid & 31;
    const int wm   = wid & 3,  wn   = wid >> 2;
    const int g    = lane >> 2, t   = lane & 3;
    const int ldr  = tid >> 3, ldkq = tid & 7;   // loader row base / 16B chunk

    uint32_t as_s = (uint32_t)__cvta_generic_to_shared(As);
    uint32_t ws_s = (uint32_t)__cvta_generic_to_shared(Ws);

    float4 acc[2][8];
#pragma unroll
    for (int mi = 0; mi < 2; mi++)
#pragma unroll
        for (int ni = 0; ni < 8; ni++) acc[mi][ni] = make_float4(0.f,0.f,0.f,0.f);

    auto prefetch = [&](int kt, int stg) {
        int k0 = kt * 32;
#pragma unroll
        for (int i = 0; i < 4; i++) {
            int r = ldr + i*32;
            cpasync16(as_s + (stg*GSTG + r*36 + ldkq*4)*4,
                      A + (size_t)(m0+r)*K + k0 + ldkq*4);
            cpasync16(ws_s + (stg*GSTG + r*36 + ldkq*4)*4,
                      W + (size_t)r*K + k0 + ldkq*4);
        }
        asm volatile("cp.async.commit_group;" ::: "memory");
    };

    const int NT = K / 32;
    prefetch(0, 0);
    for (int kt = 0; kt < NT; kt++) {
        if (kt + 1 < NT) {
            prefetch(kt + 1, (kt + 1) & 1);
            asm volatile("cp.async.wait_group 1;" ::: "memory");
        } else {
            asm volatile("cp.async.wait_group 0;" ::: "memory");
        }
        __syncthreads();

        const uint32_t* Ast = As + (kt & 1)*GSTG;
        const uint32_t* Wst = Ws + (kt & 1)*GSTG;
#pragma unroll
        for (int kb = 0; kb < 32; kb += 8) {
            uint32_t a[2][4];
#pragma unroll
            for (int mi = 0; mi < 2; mi++) {
                int R = wm*32 + mi*16;
                a[mi][0] = Ast[(R + g    )*36 + kb + t    ];
                a[mi][1] = Ast[(R + g + 8)*36 + kb + t    ];
                a[mi][2] = Ast[(R + g    )*36 + kb + t + 4];
                a[mi][3] = Ast[(R + g + 8)*36 + kb + t + 4];
            }
#pragma unroll
            for (int ni = 0; ni < 8; ni++) {
                int N8 = wn*64 + ni*8;
                uint32_t b0 = Wst[(N8 + g)*36 + kb + t    ];
                uint32_t b1 = Wst[(N8 + g)*36 + kb + t + 4];
                mma_tf32(acc[0][ni], a[0][0], a[0][1], a[0][2], a[0][3], b0, b1);
                mma_tf32(acc[1][ni], a[1][0], a[1][1], a[1][2], a[1][3], b0, b1);
            }
        }
        __syncthreads();
    }

#pragma unroll
    for (int ni = 0; ni < 8; ni++) {
        int ncl = wn*64 + ni*8 + 2*t;
        float2 bv = *(const float2*)(bias + ncl);
#pragma unroll
        for (int mi = 0; mi < 2; mi++) {
            float4 cf = acc[mi][ni];
            int r0 = m0 + wm*32 + mi*16 + g;
            float2 o0 = { cf.x + bv.x, cf.y + bv.y };
            float2 o1 = { cf.z + bv.x, cf.w + bv.y };
            *(float2*)(Z + (size_t)r0*1024 + n0 + ncl)     = o0;
            *(float2*)(Z + (size_t)(r0+8)*1024 + n0 + ncl) = o1;
        }
    }
}

// ---------------- recurrence: R12-proven (unchanged) -------------------------
#define RSMEM (65536 + 1024)

template<int LAYER>
__global__ void __launch_bounds__(512, 1) recur_kernel(
    const float* __restrict__ whhf, const float* __restrict__ whhb)
{
    extern __shared__ char smraw[];
    u64*   wsm = (u64*)smraw;                       // [8 p][512 tid][2]
    float* hs  = (float*)(smraw + 65536);           // [2][128] double buffer

    const int tid  = threadIdx.x;
    const int w    = tid >> 5;
    const int l    = tid & 31;
    const int uoff = l & 7;
    const int row  = (l >> 3)*128 + w*8 + uoff;     // Whh row (gate*128 + unit)
    const int u    = w*8 + uoff;                    // unit
    const int cell = blockIdx.x >> 6;
    const int b    = blockIdx.x & 63;
    const float* whh = cell ? whhb : whhf;
    const float* zx  = LAYER ? g_zx1 : g_zx0;
    float*       ys  = LAYER ? g_ys1 : g_ys0;

    const u64* wrow = (const u64*)whh + (size_t)row*64;
    u64 wreg[48];
#pragma unroll
    for (int q = 0; q < 48; q++) wreg[q] = __ldg(wrow + q);
#pragma unroll
    for (int p = 0; p < 8; p++) {
        wsm[(p*512 + tid)*2 + 0] = __ldg(wrow + 48 + 2*p);
        wsm[(p*512 + tid)*2 + 1] = __ldg(wrow + 48 + 2*p + 1);
    }

    if (tid < 128) hs[tid] = 0.f;                   // read buffer for t=0

    uint32_t hs_s  = (uint32_t)__cvta_generic_to_shared(hs);
    uint32_t wsm_s = (uint32_t)__cvta_generic_to_shared(wsm);

    const float* zptr = zx + (size_t)b*1024 + cell*512 + row;
    float* ysp = ys + (size_t)b*256 + cell*128 + u;
    float zcur = __ldcs(zptr);
    float c = 0.f;

    __syncthreads();

    for (int t = 0; t < SEQ; t++) {
        float znext = __ldcs(zptr + (size_t)(t+1)*65536);
        uint32_t hb = hs_s + (t & 1)*512;           // current read buffer

        u64 a0 = 0ull, a1 = 0ull, a2 = 0ull, a3 = 0ull;
#pragma unroll
        for (int q = 0; q < 48; q += 2) {                   // k in [0,96)
            u64 ha, hbv;
            lds2(ha, hbv, hb + q*8);
            ffma2(a0, wreg[q],   ha);
            ffma2(a1, wreg[q+1], hbv);
        }
#pragma unroll
        for (int p = 0; p < 8; p++) {                       // k in [96,128)
            u64 ha, hbv, wa, wb;
            lds2(ha, hbv, hb + 384 + p*16);
            lds2(wa, wb, wsm_s + (p*512 + tid)*16);
            ffma2(a2, wa, ha);
            ffma2(a3, wb, hbv);
        }
        float x0,x1,x2,x3,y0,y1,y2,y3;
        unpk(x0,x1,a0); unpk(x2,x3,a1);
        unpk(y0,y1,a2); unpk(y2,y3,a3);
        float s = (((x0+x1)+(x2+x3)) + ((y0+y1)+(y2+y3))) + zcur;
        zcur = znext;

        float zi = __shfl_sync(0xffffffffu, s, uoff);
        float zf = __shfl_sync(0xffffffffu, s, uoff | 8);
        float zg = __shfl_sync(0xffffffffu, s, uoff | 16);
        float zo = __shfl_sync(0xffffffffu, s, uoff | 24);
        float ig = sigma_fast(zi), fg = sigma_fast(zf);
        float gg = tanha(zg),      og = sigma_fast(zo);
        c = fg*c + ig*gg;
        float h = og * tanha(c);
        if (l < 8) {
            ((float*)(smraw + 65536))[((t+1)&1)*128 + u] = h;
            ysp[(size_t)t*16384] = h;
        }
        __syncthreads();
    }
}

// ---------------- final FC + sigmoid ----------------------------------------
__global__ void __launch_bounds__(256) fc_kernel(
    const float* __restrict__ fcw, const float* __restrict__ fcb,
    float* __restrict__ out)
{
    int gtid = blockIdx.x*blockDim.x + threadIdx.x;
    int row = gtid >> 5, lane = gtid & 31;
    if (row >= NROWS) return;
    const float* y = g_ys1 + (size_t)row*256;
    float s = 0.f;
#pragma unroll
    for (int i = 0; i < 8; i++) s += y[lane + i*32] * __ldg(fcw + lane + i*32);
#pragma unroll
    for (int o = 16; o; o >>= 1) s += __shfl_xor_sync(0xffffffffu, s, o);
    if (lane == 0) out[row] = sigm(s + fcb[0]);
}

// ---------------- launch -----------------------------------------------------
extern "C" void kernel_launch(void* const* d_in, const int* in_sizes, int n_in,
                              void* d_out, int out_size)
{
    const float* x     = (const float*)d_in[0];
    const float* wih0f = (const float*)d_in[1];
    const float* whh0f = (const float*)d_in[2];
    const float* b0f   = (const float*)d_in[3];
    const float* wih0b = (const float*)d_in[4];
    const float* whh0b = (const float*)d_in[5];
    const float* b0b   = (const float*)d_in[6];
    const float* wih1f = (const float*)d_in[7];
    const float* whh1f = (const float*)d_in[8];
    const float* b1f   = (const float*)d_in[9];
    const float* wih1b = (const float*)d_in[10];
    const float* whh1b = (const float*)d_in[11];
    const float* b1b   = (const float*)d_in[12];
    const float* fcw   = (const float*)d_in[13];
    const float* fcb   = (const float*)d_in[14];
    float* out = (float*)d_out;

    cudaFuncSetAttribute(mma_gemm<DIM, 0>, cudaFuncAttributeMaxDynamicSharedMemorySize, GSMEM);
    cudaFuncSetAttribute(mma_gemm<256, 1>, cudaFuncAttributeMaxDynamicSharedMemorySize, GSMEM);
    cudaFuncSetAttribute(recur_kernel<0>, cudaFuncAttributeMaxDynamicSharedMemorySize, RSMEM);
    cudaFuncSetAttribute(recur_kernel<1>, cudaFuncAttributeMaxDynamicSharedMemorySize, RSMEM);

    dim3 ggrid(8, NROWS/128);
    mma_gemm<DIM, 0><<<ggrid, 256, GSMEM>>>(x, wih0f, wih0b, b0f, b0b);
    recur_kernel<0><<<128, 512, RSMEM>>>(whh0f, whh0b);

    mma_gemm<256, 1><<<ggrid, 256, GSMEM>>>(nullptr, wih1f, wih1b, b1f, b1b);
    recur_kernel<1><<<128, 512, RSMEM>>>(whh1f, whh1b);

    fc_kernel<<<(NROWS*32)/256, 256>>>(fcw, fcb, out);
}

// round 14
// speedup vs baseline: 5.6111x; 1.2257x over previous
#include <cuda_runtime.h>
#include <cstdint>

#define SEQ   4096
#define BATCH 64
#define DIM   96
#define HID   128
#define NROWS (SEQ*BATCH)

using u64 = unsigned long long;

// ---------------- scratch (static device globals) ---------------------------
__device__ float g_zx0[(size_t)NROWS*1024 + 65536];  // [row=t*64+b][n], +1 step pad
__device__ float g_zx1[(size_t)NROWS*1024 + 65536];
__device__ float g_ys0[(size_t)NROWS*256];           // [t][b][2H]
__device__ float g_ys1[(size_t)NROWS*256];

// ---------------- helpers ----------------------------------------------------
__device__ __forceinline__ float sigm(float x)   { return 1.f/(1.f+__expf(-x)); }
__device__ __forceinline__ float tanha(float x)  {
    float r; asm("tanh.approx.f32 %0, %1;" : "=f"(r) : "f"(x)); return r;
}
__device__ __forceinline__ float sigma_fast(float x) {
    return fmaf(0.5f, tanha(0.5f*x), 0.5f);
}
__device__ __forceinline__ void ffma2(u64 &d, u64 a, u64 b) {
    asm volatile("fma.rn.f32x2 %0, %1, %2, %0;" : "+l"(d) : "l"(a), "l"(b));
}
__device__ __forceinline__ void lds2(u64 &a, u64 &b, uint32_t addr) {
    asm volatile("ld.shared.v2.u64 {%0,%1}, [%2];" : "=l"(a), "=l"(b) : "r"(addr));
}
__device__ __forceinline__ void unpk(float &lo, float &hi, u64 v) {
    asm volatile("mov.b64 {%0,%1}, %2;" : "=f"(lo), "=f"(hi) : "l"(v));
}
__device__ __forceinline__ void cpasync16(uint32_t dst, const void* src) {
    asm volatile("cp.async.ca.shared.global [%0], [%1], 16;" :: "r"(dst), "l"(src));
}
__device__ __forceinline__ void mma_tf32(float4 &c,
    uint32_t a0, uint32_t a1, uint32_t a2, uint32_t a3,
    uint32_t b0, uint32_t b1)
{
    asm volatile("mma.sync.aligned.m16n8k8.row.col.f32.tf32.tf32.f32 "
        "{%0,%1,%2,%3}, {%4,%5,%6,%7}, {%8,%9}, {%0,%1,%2,%3};"
        : "+f"(c.x), "+f"(c.y), "+f"(c.z), "+f"(c.w)
        : "r"(a0), "r"(a1), "r"(a2), "r"(a3), "r"(b0), "r"(b1));
}

// ---------------- input-projection GEMM: R13 proven (cp.async pipeline) ------
#define GSTG 4608
#define GSMEM (4*GSTG*4)

template<int K, int LAYER>
__global__ void __launch_bounds__(256, 2) mma_gemm(
    const float* __restrict__ Aext,
    const float* __restrict__ Wf, const float* __restrict__ Wb,
    const float* __restrict__ bf, const float* __restrict__ bb)
{
    extern __shared__ uint32_t gsm[];
    uint32_t* As = gsm;
    uint32_t* Ws = gsm + 2*GSTG;

    const float* A = (LAYER == 0) ? Aext : (const float*)g_ys0;
    float*       Z = LAYER ? g_zx1 : g_zx0;

    const int n0 = blockIdx.x * 128;
    const int m0 = blockIdx.y * 128;
    const float* W    = (n0 < 512) ? (Wf + (size_t)n0*K) : (Wb + (size_t)(n0-512)*K);
    const float* bias = (n0 < 512) ? (bf + n0) : (bb + (n0-512));

    const int tid  = threadIdx.x;
    const int wid  = tid >> 5, lane = tid & 31;
    const int wm   = wid & 3,  wn   = wid >> 2;
    const int g    = lane >> 2, t   = lane & 3;
    const int ldr  = tid >> 3, ldkq = tid & 7;

    uint32_t as_s = (uint32_t)__cvta_generic_to_shared(As);
    uint32_t ws_s = (uint32_t)__cvta_generic_to_shared(Ws);

    float4 acc[2][8];
#pragma unroll
    for (int mi = 0; mi < 2; mi++)
#pragma unroll
        for (int ni = 0; ni < 8; ni++) acc[mi][ni] = make_float4(0.f,0.f,0.f,0.f);

    auto prefetch = [&](int kt, int stg) {
        int k0 = kt * 32;
#pragma unroll
        for (int i = 0; i < 4; i++) {
            int r = ldr + i*32;
            cpasync16(as_s + (stg*GSTG + r*36 + ldkq*4)*4,
                      A + (size_t)(m0+r)*K + k0 + ldkq*4);
            cpasync16(ws_s + (stg*GSTG + r*36 + ldkq*4)*4,
                      W + (size_t)r*K + k0 + ldkq*4);
        }
        asm volatile("cp.async.commit_group;" ::: "memory");
    };

    const int NT = K / 32;
    prefetch(0, 0);
    for (int kt = 0; kt < NT; kt++) {
        if (kt + 1 < NT) {
            prefetch(kt + 1, (kt + 1) & 1);
            asm volatile("cp.async.wait_group 1;" ::: "memory");
        } else {
            asm volatile("cp.async.wait_group 0;" ::: "memory");
        }
        __syncthreads();

        const uint32_t* Ast = As + (kt & 1)*GSTG;
        const uint32_t* Wst = Ws + (kt & 1)*GSTG;
#pragma unroll
        for (int kb = 0; kb < 32; kb += 8) {
            uint32_t a[2][4];
#pragma unroll
            for (int mi = 0; mi < 2; mi++) {
                int R = wm*32 + mi*16;
                a[mi][0] = Ast[(R + g    )*36 + kb + t    ];
                a[mi][1] = Ast[(R + g + 8)*36 + kb + t    ];
                a[mi][2] = Ast[(R + g    )*36 + kb + t + 4];
                a[mi][3] = Ast[(R + g + 8)*36 + kb + t + 4];
            }
#pragma unroll
            for (int ni = 0; ni < 8; ni++) {
                int N8 = wn*64 + ni*8;
                uint32_t b0 = Wst[(N8 + g)*36 + kb + t    ];
                uint32_t b1 = Wst[(N8 + g)*36 + kb + t + 4];
                mma_tf32(acc[0][ni], a[0][0], a[0][1], a[0][2], a[0][3], b0, b1);
                mma_tf32(acc[1][ni], a[1][0], a[1][1], a[1][2], a[1][3], b0, b1);
            }
        }
        __syncthreads();
    }

#pragma unroll
    for (int ni = 0; ni < 8; ni++) {
        int ncl = wn*64 + ni*8 + 2*t;
        float2 bv = *(const float2*)(bias + ncl);
#pragma unroll
        for (int mi = 0; mi < 2; mi++) {
            float4 cf = acc[mi][ni];
            int r0 = m0 + wm*32 + mi*16 + g;
            float2 o0 = { cf.x + bv.x, cf.y + bv.y };
            float2 o1 = { cf.z + bv.x, cf.w + bv.y };
            *(float2*)(Z + (size_t)r0*1024 + n0 + ncl)     = o0;
            *(float2*)(Z + (size_t)(r0+8)*1024 + n0 + ncl) = o1;
        }
    }
}

// ---------------- recurrence: split-k-in-warp --------------------------------
// 128 CTAs x 512 threads. Warp w owns units [8w,8w+8). Lane l: uoff=l&7,
// g01=(l>>3)&1, half=l>>4. Thread computes the k-half [64*half,64*half+64) of
// TWO rows: r_a = g01*128+8w+uoff (gates 0/1), r_b = r_a+256 (gates 2/3).
// h-loads: 16 LDS.128 per thread (HALF of before); halves merge per instr
// (h stored [2][132], half-1 at +272B -> conflict-free dual broadcast).
// Weights: r_a 32 pairs + r_b 16 pairs in regs; r_b pairs 16..31 in smem
// ([8 s][512 tid][2]). Combine: shfl.xor 16 (halves) + shfl.xor 8 (gates).
// Epilogue redundant x4; lanes l<8 write h+ys. 1 barrier/step.
#define RSMEM (65536 + 1088)

template<int LAYER>
__global__ void __launch_bounds__(512, 1) recur_kernel(
    const float* __restrict__ whhf, const float* __restrict__ whhb)
{
    extern __shared__ char smraw[];
    u64*   wsm = (u64*)smraw;                       // [8 s][512 tid][2]
    float* hs  = (float*)(smraw + 65536);           // [2][132] (+4 pad per buf)

    const int tid  = threadIdx.x;
    const int w    = tid >> 5;
    const int l    = tid & 31;
    const int uoff = l & 7;
    const int g01  = (l >> 3) & 1;
    const int half = l >> 4;
    const int u    = w*8 + uoff;
    const int r_a  = g01*128 + u;                   // gate g01
    const int r_b  = r_a + 256;                     // gate g01+2
    const int cell = blockIdx.x >> 6;
    const int b    = blockIdx.x & 63;
    const float* whh = cell ? whhb : whhf;
    const float* zx  = LAYER ? g_zx1 : g_zx0;
    float*       ys  = LAYER ? g_ys1 : g_ys0;

    // weights for this thread's k-half
    const u64* wra = (const u64*)whh + (size_t)r_a*64 + half*32;  // 32 pairs
    const u64* wrb = (const u64*)whh + (size_t)r_b*64 + half*32;  // 32 pairs
    u64 wa[32], wb[16];
#pragma unroll
    for (int q = 0; q < 32; q++) wa[q] = __ldg(wra + q);
#pragma unroll
    for (int q = 0; q < 16; q++) wb[q] = __ldg(wrb + q);
#pragma unroll
    for (int s = 0; s < 8; s++) {                   // r_b pairs 16..31 -> smem
        wsm[(s*512 + tid)*2 + 0] = __ldg(wrb + 16 + 2*s);
        wsm[(s*512 + tid)*2 + 1] = __ldg(wrb + 16 + 2*s + 1);
    }

    if (tid < 264) hs[tid] = 0.f;                   // both buffers + pads

    uint32_t hs_s  = (uint32_t)__cvta_generic_to_shared(hs);
    uint32_t wsm_s = (uint32_t)__cvta_generic_to_shared(wsm);
    const uint32_t hofs = half*272;                 // byte offset of my half

    const float* zpa = zx + (size_t)b*1024 + cell*512 + r_a;
    const float* zpb = zx + (size_t)b*1024 + cell*512 + r_b;
    float* ysp = ys + (size_t)b*256 + cell*128 + u;
    float zca = __ldcs(zpa), zcb = __ldcs(zpb);
    float c = 0.f;
    const int hw = u + ((u >= 64) ? 4 : 0);         // padded h index for writer

    __syncthreads();

    for (int t = 0; t < SEQ; t++) {
        float zna = __ldcs(zpa + (size_t)(t+1)*65536);
        float znb = __ldcs(zpb + (size_t)(t+1)*65536);
        uint32_t hb = hs_s + (t & 1)*528 + hofs;    // my half of read buffer

        u64 aa0 = 0ull, aa1 = 0ull, ab0 = 0ull, ab1 = 0ull;
#pragma unroll
        for (int q = 0; q < 8; q++) {               // k-half pairs 0..15
            u64 ha, hv;
            lds2(ha, hv, hb + q*16);
            ffma2(aa0, wa[2*q],   ha);
            ffma2(aa1, wa[2*q+1], hv);
            ffma2(ab0, wb[2*q],   ha);
            ffma2(ab1, wb[2*q+1], hv);
        }
#pragma unroll
        for (int q = 8; q < 16; q++) {              // k-half pairs 16..31
            u64 ha, hv, va, vb;
            lds2(ha, hv, hb + q*16);
            lds2(va, vb, wsm_s + ((q-8)*512 + tid)*16);
            ffma2(aa0, wa[2*q],   ha);
            ffma2(aa1, wa[2*q+1], hv);
            ffma2(ab0, va, ha);
            ffma2(ab1, vb, hv);
        }
        float x0,x1,x2,x3;
        unpk(x0,x1,aa0); unpk(x2,x3,aa1);
        float sa = (x0+x1) + (x2+x3);
        unpk(x0,x1,ab0); unpk(x2,x3,ab1);
        float sb = (x0+x1) + (x2+x3);

        sa += __shfl_xor_sync(0xffffffffu, sa, 16); // combine k-halves
        sb += __shfl_xor_sync(0xffffffffu, sb, 16);
        sa += zca;  sb += zcb;
        zca = zna;  zcb = znb;

        float ta = __shfl_xor_sync(0xffffffffu, sa, 8);  // gate exchange
        float tb = __shfl_xor_sync(0xffffffffu, sb, 8);
        float zi = g01 ? ta : sa;
        float zf = g01 ? sa : ta;
        float zg = g01 ? tb : sb;
        float zo = g01 ? sb : tb;

        float ig = sigma_fast(zi), fg = sigma_fast(zf);
        float gg = tanha(zg),      og = sigma_fast(zo);
        c = fg*c + ig*gg;                           // redundant x4 (g01,half)
        float h = og * tanha(c);
        if (l < 8) {
            hs[((t+1)&1)*132 + hw] = h;
            ysp[(size_t)t*16384] = h;
        }
        __syncthreads();
    }
}

// ---------------- final FC + sigmoid ----------------------------------------
__global__ void __launch_bounds__(256) fc_kernel(
    const float* __restrict__ fcw, const float* __restrict__ fcb,
    float* __restrict__ out)
{
    int gtid = blockIdx.x*blockDim.x + threadIdx.x;
    int row = gtid >> 5, lane = gtid & 31;
    if (row >= NROWS) return;
    const float* y = g_ys1 + (size_t)row*256;
    float s = 0.f;
#pragma unroll
    for (int i = 0; i < 8; i++) s += y[lane + i*32] * __ldg(fcw + lane + i*32);
#pragma unroll
    for (int o = 16; o; o >>= 1) s += __shfl_xor_sync(0xffffffffu, s, o);
    if (lane == 0) out[row] = sigm(s + fcb[0]);
}

// ---------------- launch -----------------------------------------------------
extern "C" void kernel_launch(void* const* d_in, const int* in_sizes, int n_in,
                              void* d_out, int out_size)
{
    const float* x     = (const float*)d_in[0];
    const float* wih0f = (const float*)d_in[1];
    const float* whh0f = (const float*)d_in[2];
    const float* b0f   = (const float*)d_in[3];
    const float* wih0b = (const float*)d_in[4];
    const float* whh0b = (const float*)d_in[5];
    const float* b0b   = (const float*)d_in[6];
    const float* wih1f = (const float*)d_in[7];
    const float* whh1f = (const float*)d_in[8];
    const float* b1f   = (const float*)d_in[9];
    const float* wih1b = (const float*)d_in[10];
    const float* whh1b = (const float*)d_in[11];
    const float* b1b   = (const float*)d_in[12];
    const float* fcw   = (const float*)d_in[13];
    const float* fcb   = (const float*)d_in[14];
    float* out = (float*)d_out;

    cudaFuncSetAttribute(mma_gemm<DIM, 0>, cudaFuncAttributeMaxDynamicSharedMemorySize, GSMEM);
    cudaFuncSetAttribute(mma_gemm<256, 1>, cudaFuncAttributeMaxDynamicSharedMemorySize, GSMEM);
    cudaFuncSetAttribute(recur_kernel<0>, cudaFuncAttributeMaxDynamicSharedMemorySize, RSMEM);
    cudaFuncSetAttribute(recur_kernel<1>, cudaFuncAttributeMaxDynamicSharedMemorySize, RSMEM);

    dim3 ggrid(8, NROWS/128);
    mma_gemm<DIM, 0><<<ggrid, 256, GSMEM>>>(x, wih0f, wih0b, b0f, b0b);
    recur_kernel<0><<<128, 512, RSMEM>>>(whh0f, whh0b);

    mma_gemm<256, 1><<<ggrid, 256, GSMEM>>>(nullptr, wih1f, wih1b, b1f, b1b);
    recur_kernel<1><<<128, 512, RSMEM>>>(whh1f, whh1b);

    fc_kernel<<<(NROWS*32)/256, 256>>>(fcw, fcb, out);
}

// round 15
// speedup vs baseline: 6.0138x; 1.0718x over previous
#include <cuda_runtime.h>
#include <cstdint>

#define SEQ   4096
#define BATCH 64
#define DIM   96
#define HID   128
#define NROWS (SEQ*BATCH)

using u64 = unsigned long long;

// ---------------- scratch (static device globals) ---------------------------
__device__ float g_zx0[(size_t)NROWS*1024 + 65536];  // [row=t*64+b][n], +1 step pad
__device__ float g_zx1[(size_t)NROWS*1024 + 65536];
__device__ float g_ys0[(size_t)NROWS*256];           // [t][b][2H]
__device__ float g_ys1[(size_t)NROWS*256];

// ---------------- helpers ----------------------------------------------------
__device__ __forceinline__ float sigm(float x)   { return 1.f/(1.f+__expf(-x)); }
__device__ __forceinline__ float tanha(float x)  {
    float r; asm("tanh.approx.f32 %0, %1;" : "=f"(r) : "f"(x)); return r;
}
__device__ __forceinline__ float sigma_fast(float x) {
    return fmaf(0.5f, tanha(0.5f*x), 0.5f);
}
__device__ __forceinline__ void ffma2(u64 &d, u64 a, u64 b) {
    asm volatile("fma.rn.f32x2 %0, %1, %2, %0;" : "+l"(d) : "l"(a), "l"(b));
}
__device__ __forceinline__ void lds2(u64 &a, u64 &b, uint32_t addr) {
    asm volatile("ld.shared.v2.u64 {%0,%1}, [%2];" : "=l"(a), "=l"(b) : "r"(addr));
}
__device__ __forceinline__ void unpk(float &lo, float &hi, u64 v) {
    asm volatile("mov.b64 {%0,%1}, %2;" : "=f"(lo), "=f"(hi) : "l"(v));
}
__device__ __forceinline__ void cpasync16(uint32_t dst, const void* src) {
    asm volatile("cp.async.ca.shared.global [%0], [%1], 16;" :: "r"(dst), "l"(src));
}
__device__ __forceinline__ void mma_tf32(float4 &c,
    uint32_t a0, uint32_t a1, uint32_t a2, uint32_t a3,
    uint32_t b0, uint32_t b1)
{
    asm volatile("mma.sync.aligned.m16n8k8.row.col.f32.tf32.tf32.f32 "
        "{%0,%1,%2,%3}, {%4,%5,%6,%7}, {%8,%9}, {%0,%1,%2,%3};"
        : "+f"(c.x), "+f"(c.y), "+f"(c.z), "+f"(c.w)
        : "r"(a0), "r"(a1), "r"(a2), "r"(a3), "r"(b0), "r"(b1));
}

// ---------------- input-projection GEMM: R13 proven (cp.async pipeline) ------
#define GSTG 4608
#define GSMEM (4*GSTG*4)

template<int K, int LAYER>
__global__ void __launch_bounds__(256, 2) mma_gemm(
    const float* __restrict__ Aext,
    const float* __restrict__ Wf, const float* __restrict__ Wb,
    const float* __restrict__ bf, const float* __restrict__ bb)
{
    extern __shared__ uint32_t gsm[];
    uint32_t* As = gsm;
    uint32_t* Ws = gsm + 2*GSTG;

    const float* A = (LAYER == 0) ? Aext : (const float*)g_ys0;
    float*       Z = LAYER ? g_zx1 : g_zx0;

    const int n0 = blockIdx.x * 128;
    const int m0 = blockIdx.y * 128;
    const float* W    = (n0 < 512) ? (Wf + (size_t)n0*K) : (Wb + (size_t)(n0-512)*K);
    const float* bias = (n0 < 512) ? (bf + n0) : (bb + (n0-512));

    const int tid  = threadIdx.x;
    const int wid  = tid >> 5, lane = tid & 31;
    const int wm   = wid & 3,  wn   = wid >> 2;
    const int g    = lane >> 2, t   = lane & 3;
    const int ldr  = tid >> 3, ldkq = tid & 7;

    uint32_t as_s = (uint32_t)__cvta_generic_to_shared(As);
    uint32_t ws_s = (uint32_t)__cvta_generic_to_shared(Ws);

    float4 acc[2][8];
#pragma unroll
    for (int mi = 0; mi < 2; mi++)
#pragma unroll
        for (int ni = 0; ni < 8; ni++) acc[mi][ni] = make_float4(0.f,0.f,0.f,0.f);

    auto prefetch = [&](int kt, int stg) {
        int k0 = kt * 32;
#pragma unroll
        for (int i = 0; i < 4; i++) {
            int r = ldr + i*32;
            cpasync16(as_s + (stg*GSTG + r*36 + ldkq*4)*4,
                      A + (size_t)(m0+r)*K + k0 + ldkq*4);
            cpasync16(ws_s + (stg*GSTG + r*36 + ldkq*4)*4,
                      W + (size_t)r*K + k0 + ldkq*4);
        }
        asm volatile("cp.async.commit_group;" ::: "memory");
    };

    const int NT = K / 32;
    prefetch(0, 0);
    for (int kt = 0; kt < NT; kt++) {
        if (kt + 1 < NT) {
            prefetch(kt + 1, (kt + 1) & 1);
            asm volatile("cp.async.wait_group 1;" ::: "memory");
        } else {
            asm volatile("cp.async.wait_group 0;" ::: "memory");
        }
        __syncthreads();

        const uint32_t* Ast = As + (kt & 1)*GSTG;
        const uint32_t* Wst = Ws + (kt & 1)*GSTG;
#pragma unroll
        for (int kb = 0; kb < 32; kb += 8) {
            uint32_t a[2][4];
#pragma unroll
            for (int mi = 0; mi < 2; mi++) {
                int R = wm*32 + mi*16;
                a[mi][0] = Ast[(R + g    )*36 + kb + t    ];
                a[mi][1] = Ast[(R + g + 8)*36 + kb + t    ];
                a[mi][2] = Ast[(R + g    )*36 + kb + t + 4];
                a[mi][3] = Ast[(R + g + 8)*36 + kb + t + 4];
            }
#pragma unroll
            for (int ni = 0; ni < 8; ni++) {
                int N8 = wn*64 + ni*8;
                uint32_t b0 = Wst[(N8 + g)*36 + kb + t    ];
                uint32_t b1 = Wst[(N8 + g)*36 + kb + t + 4];
                mma_tf32(acc[0][ni], a[0][0], a[0][1], a[0][2], a[0][3], b0, b1);
                mma_tf32(acc[1][ni], a[1][0], a[1][1], a[1][2], a[1][3], b0, b1);
            }
        }
        __syncthreads();
    }

#pragma unroll
    for (int ni = 0; ni < 8; ni++) {
        int ncl = wn*64 + ni*8 + 2*t;
        float2 bv = *(const float2*)(bias + ncl);
#pragma unroll
        for (int mi = 0; mi < 2; mi++) {
            float4 cf = acc[mi][ni];
            int r0 = m0 + wm*32 + mi*16 + g;
            float2 o0 = { cf.x + bv.x, cf.y + bv.y };
            float2 o1 = { cf.z + bv.x, cf.w + bv.y };
            *(float2*)(Z + (size_t)r0*1024 + n0 + ncl)     = o0;
            *(float2*)(Z + (size_t)(r0+8)*1024 + n0 + ncl) = o1;
        }
    }
}

// ---------------- recurrence: quarter-split-k --------------------------------
// 128 CTAs x 512 threads. Warp w owns units [8w,8w+8). Lane l: uoff=l&7,
// q=l>>3 (k-quarter). Thread computes k-quarter [32q,32q+32) of ALL 4 gate
// rows of unit u=8w+uoff. Weights: gates 0..2 in 48 reg pairs, gate 3's 16
// pairs in smem [8 p][512 tid][2]. h stored quarter-skewed (36 words/quarter)
// so each h LDS.128 is 1 wavefront (4 distinct 16B chunks across quarters).
// Quarter-reduce: shfl.xor 8 + shfl.xor 16 per gate; z[gate q] added by
// quarter q pre-reduction. Epilogue redundant x4; lanes q=0 write h + ys.
#define RSMEM (65536 + 1280)

template<int LAYER>
__global__ void __launch_bounds__(512, 1) recur_kernel(
    const float* __restrict__ whhf, const float* __restrict__ whhb)
{
    extern __shared__ char smraw[];
    u64*   wsm = (u64*)smraw;                       // [8 p][512 tid][2]
    float* hs  = (float*)(smraw + 65536);           // [2][160] quarter-skewed

    const int tid  = threadIdx.x;
    const int w    = tid >> 5;
    const int l    = tid & 31;
    const int uoff = l & 7;
    const int q    = l >> 3;                        // k-quarter 0..3
    const int u    = w*8 + uoff;                    // unit
    const int cell = blockIdx.x >> 6;
    const int b    = blockIdx.x & 63;
    const float* whh = cell ? whhb : whhf;
    const float* zx  = LAYER ? g_zx1 : g_zx0;
    float*       ys  = LAYER ? g_ys1 : g_ys0;

    // weights: gate g row = g*128+u, k-quarter q -> pairs [q*16, q*16+16)
    u64 wreg[48];                                   // gates 0..2
#pragma unroll
    for (int g = 0; g < 3; g++) {
        const u64* wr = (const u64*)whh + (size_t)(g*128 + u)*64 + q*16;
#pragma unroll
        for (int p = 0; p < 16; p++) wreg[g*16 + p] = __ldg(wr + p);
    }
    {                                               // gate 3 -> smem
        const u64* wr = (const u64*)whh + (size_t)(3*128 + u)*64 + q*16;
#pragma unroll
        for (int p = 0; p < 8; p++) {
            wsm[(p*512 + tid)*2 + 0] = __ldg(wr + 2*p);
            wsm[(p*512 + tid)*2 + 1] = __ldg(wr + 2*p + 1);
        }
    }

    if (tid < 320) hs[tid] = 0.f;                   // both buffers

    uint32_t hs_s  = (uint32_t)__cvta_generic_to_shared(hs);
    uint32_t wsm_s = (uint32_t)__cvta_generic_to_shared(wsm);

    // z: quarter q adds gate-q's z (row = q*128 + u)
    const float* zptr = zx + (size_t)b*1024 + cell*512 + q*128 + u;
    float* ysp = ys + (size_t)b*256 + cell*128 + u;
    float zcur = __ldcs(zptr);
    float c = 0.f;
    const int hw = (u >> 5)*36 + (u & 31);          // skewed h word index

    __syncthreads();

    for (int t = 0; t < SEQ; t++) {
        float znext = __ldcs(zptr + (size_t)(t+1)*65536);
        uint32_t hb = hs_s + (t & 1)*640 + q*144;   // my quarter of read buf

        u64 a0 = 0ull, a1 = 0ull, a2 = 0ull, a3 = 0ull;
#pragma unroll
        for (int p = 0; p < 8; p++) {
            u64 ha, hv, va, vb;
            lds2(ha, hv, hb + p*16);                        // 2 h pairs
            lds2(va, vb, wsm_s + (p*512 + tid)*16);         // gate-3 pairs
            ffma2(a0, wreg[2*p],      ha);
            ffma2(a0, wreg[2*p+1],    hv);
            ffma2(a1, wreg[16+2*p],   ha);
            ffma2(a1, wreg[16+2*p+1], hv);
            ffma2(a2, wreg[32+2*p],   ha);
            ffma2(a2, wreg[32+2*p+1], hv);
            ffma2(a3, va, ha);
            ffma2(a3, vb, hv);
        }
        float x0,x1,x2,x3;
        unpk(x0,x1,a0); unpk(x2,x3,a0);  // (unpk is cheap mov)
        unpk(x0,x1,a0);
        float p0, p1, p2, p3;
        { float lo,hi; unpk(lo,hi,a0); p0 = lo+hi; }
        { float lo,hi; unpk(lo,hi,a1); p1 = lo+hi; }
        { float lo,hi; unpk(lo,hi,a2); p2 = lo+hi; }
        { float lo,hi; unpk(lo,hi,a3); p3 = lo+hi; }

        // quarter q contributes z to gate q exactly once
        if      (q == 0) p0 += zcur;
        else if (q == 1) p1 += zcur;
        else if (q == 2) p2 += zcur;
        else             p3 += zcur;
        zcur = znext;

        // reduce over quarters (lane bits 3,4)
        p0 += __shfl_xor_sync(0xffffffffu, p0, 8);
        p1 += __shfl_xor_sync(0xffffffffu, p1, 8);
        p2 += __shfl_xor_sync(0xffffffffu, p2, 8);
        p3 += __shfl_xor_sync(0xffffffffu, p3, 8);
        p0 += __shfl_xor_sync(0xffffffffu, p0, 16);
        p1 += __shfl_xor_sync(0xffffffffu, p1, 16);
        p2 += __shfl_xor_sync(0xffffffffu, p2, 16);
        p3 += __shfl_xor_sync(0xffffffffu, p3, 16);

        float ig = sigma_fast(p0), fg = sigma_fast(p1);
        float gg = tanha(p2),      og = sigma_fast(p3);
        c = fg*c + ig*gg;                           // redundant x4 (quarters)
        float h = og * tanha(c);
        if (q == 0) {
            hs[((t+1)&1)*160 + hw] = h;
            ysp[(size_t)t*16384] = h;
        }
        __syncthreads();
    }
}

// ---------------- final FC + sigmoid ----------------------------------------
__global__ void __launch_bounds__(256) fc_kernel(
    const float* __restrict__ fcw, const float* __restrict__ fcb,
    float* __restrict__ out)
{
    int gtid = blockIdx.x*blockDim.x + threadIdx.x;
    int row = gtid >> 5, lane = gtid & 31;
    if (row >= NROWS) return;
    const float* y = g_ys1 + (size_t)row*256;
    float s = 0.f;
#pragma unroll
    for (int i = 0; i < 8; i++) s += y[lane + i*32] * __ldg(fcw + lane + i*32);
#pragma unroll
    for (int o = 16; o; o >>= 1) s += __shfl_xor_sync(0xffffffffu, s, o);
    if (lane == 0) out[row] = sigm(s + fcb[0]);
}

// ---------------- launch -----------------------------------------------------
extern "C" void kernel_launch(void* const* d_in, const int* in_sizes, int n_in,
                              void* d_out, int out_size)
{
    const float* x     = (const float*)d_in[0];
    const float* wih0f = (const float*)d_in[1];
    const float* whh0f = (const float*)d_in[2];
    const float* b0f   = (const float*)d_in[3];
    const float* wih0b = (const float*)d_in[4];
    const float* whh0b = (const float*)d_in[5];
    const float* b0b   = (const float*)d_in[6];
    const float* wih1f = (const float*)d_in[7];
    const float* whh1f = (const float*)d_in[8];
    const float* b1f   = (const float*)d_in[9];
    const float* wih1b = (const float*)d_in[10];
    const float* whh1b = (const float*)d_in[11];
    const float* b1b   = (const float*)d_in[12];
    const float* fcw   = (const float*)d_in[13];
    const float* fcb   = (const float*)d_in[14];
    float* out = (float*)d_out;

    cudaFuncSetAttribute(mma_gemm<DIM, 0>, cudaFuncAttributeMaxDynamicSharedMemorySize, GSMEM);
    cudaFuncSetAttribute(mma_gemm<256, 1>, cudaFuncAttributeMaxDynamicSharedMemorySize, GSMEM);
    cudaFuncSetAttribute(recur_kernel<0>, cudaFuncAttributeMaxDynamicSharedMemorySize, RSMEM);
    cudaFuncSetAttribute(recur_kernel<1>, cudaFuncAttributeMaxDynamicSharedMemorySize, RSMEM);

    dim3 ggrid(8, NROWS/128);
    mma_gemm<DIM, 0><<<ggrid, 256, GSMEM>>>(x, wih0f, wih0b, b0f, b0b);
    recur_kernel<0><<<128, 512, RSMEM>>>(whh0f, whh0b);

    mma_gemm<256, 1><<<ggrid, 256, GSMEM>>>(nullptr, wih1f, wih1b, b1f, b1b);
    recur_kernel<1><<<128, 512, RSMEM>>>(whh1f, whh1b);

    fc_kernel<<<(NROWS*32)/256, 256>>>(fcw, fcb, out);
}